// round 2
// baseline (speedup 1.0000x reference)
#include <cuda_runtime.h>
#include <cstdint>

// Haar DWT2: in [B=8, C=32, H=512, W=512] f32 -> out [B, 4, C, 256, 256] f32
// Subband order: LL, LH, HL, HH (pywt dwt2 'haar').
//
// Each thread: reads 2 rows x 8 cols (4x LDG.128, streaming), writes one
// float4 to each of the 4 subbands (4x STG.128, streaming).
// All accesses fully coalesced; MLP_p1 = 4.

#define B_  8
#define C_  32
#define H_  512
#define W_  512
#define H2 (H_/2)
#define W2 (W_/2)

__global__ void __launch_bounds__(256) haar_dwt2_kernel(
    const float* __restrict__ in, float* __restrict__ out)
{
    // total threads = B*C*H2*(W2/4) = 8*32*256*64 = 4,194,304
    const int64_t tid = (int64_t)blockIdx.x * blockDim.x + threadIdx.x;

    const int wq = (int)(tid & (W2/4 - 1));             // 0..63 (4 output cols each)
    const int h2 = (int)((tid >> 6) & (H2 - 1));        // 0..255
    const int bc = (int)(tid >> 14);                    // 0..255  (b*32 + c)
    const int b  = bc >> 5;
    const int c  = bc & 31;

    // Input: rows 2*h2 and 2*h2+1, cols 8*wq .. 8*wq+7
    const int64_t in_row0 = ((int64_t)bc * H_ + 2 * h2) * W_ + 8 * wq;
    const float4 r0a = __ldcs(reinterpret_cast<const float4*>(in + in_row0));
    const float4 r0b = __ldcs(reinterpret_cast<const float4*>(in + in_row0 + 4));
    const float4 r1a = __ldcs(reinterpret_cast<const float4*>(in + in_row0 + W_));
    const float4 r1b = __ldcs(reinterpret_cast<const float4*>(in + in_row0 + W_ + 4));

    float4 LL, LH, HL, HH;
    // pair 0: (r0a.x, r0a.y) / (r1a.x, r1a.y)
    LL.x = (r0a.x + r0a.y + r1a.x + r1a.y) * 0.5f;
    LH.x = (r0a.x + r0a.y - r1a.x - r1a.y) * 0.5f;
    HL.x = (r0a.x - r0a.y + r1a.x - r1a.y) * 0.5f;
    HH.x = (r0a.x - r0a.y - r1a.x + r1a.y) * 0.5f;
    // pair 1: (r0a.z, r0a.w) / (r1a.z, r1a.w)
    LL.y = (r0a.z + r0a.w + r1a.z + r1a.w) * 0.5f;
    LH.y = (r0a.z + r0a.w - r1a.z - r1a.w) * 0.5f;
    HL.y = (r0a.z - r0a.w + r1a.z - r1a.w) * 0.5f;
    HH.y = (r0a.z - r0a.w - r1a.z + r1a.w) * 0.5f;
    // pair 2: (r0b.x, r0b.y) / (r1b.x, r1b.y)
    LL.z = (r0b.x + r0b.y + r1b.x + r1b.y) * 0.5f;
    LH.z = (r0b.x + r0b.y - r1b.x - r1b.y) * 0.5f;
    HL.z = (r0b.x - r0b.y + r1b.x - r1b.y) * 0.5f;
    HH.z = (r0b.x - r0b.y - r1b.x + r1b.y) * 0.5f;
    // pair 3: (r0b.z, r0b.w) / (r1b.z, r1b.w)
    LL.w = (r0b.z + r0b.w + r1b.z + r1b.w) * 0.5f;
    LH.w = (r0b.z + r0b.w - r1b.z - r1b.w) * 0.5f;
    HL.w = (r0b.z - r0b.w + r1b.z - r1b.w) * 0.5f;
    HH.w = (r0b.z - r0b.w - r1b.z + r1b.w) * 0.5f;

    // Output: [B, 4, C, H2, W2]
    const int64_t plane = (int64_t)H2 * W2;                       // 65536
    const int64_t obase = (((int64_t)b * 4) * C_ + c) * plane
                          + (int64_t)h2 * W2 + 4 * wq;
    const int64_t sstride = (int64_t)C_ * plane;                  // subband stride

    __stcs(reinterpret_cast<float4*>(out + obase),               LL);
    __stcs(reinterpret_cast<float4*>(out + obase + sstride),     LH);
    __stcs(reinterpret_cast<float4*>(out + obase + 2 * sstride), HL);
    __stcs(reinterpret_cast<float4*>(out + obase + 3 * sstride), HH);
}

extern "C" void kernel_launch(void* const* d_in, const int* in_sizes, int n_in,
                              void* d_out, int out_size)
{
    const float* in = (const float*)d_in[0];
    float* out = (float*)d_out;

    const int64_t total_threads = (int64_t)B_ * C_ * H2 * (W2 / 4);   // 4,194,304
    const int threads = 256;
    const int blocks = (int)(total_threads / threads);                 // 16,384

    haar_dwt2_kernel<<<blocks, threads>>>(in, out);
}

// round 3
// speedup vs baseline: 1.0058x; 1.0058x over previous
#include <cuda_runtime.h>
#include <cstdint>

// Haar DWT2: in [B=8, C=32, H=512, W=512] f32 -> out [B, 4, C, 256, 256] f32
// Subband order: LL, LH, HL, HH (pywt dwt2 'haar').
//
// Each thread: reads 4 consecutive rows x 4 cols (4x LDG.128, each warp
// instruction fully contiguous 512B), producing 2 output rows x 2 cols per
// subband (8x STG.64, each warp instruction contiguous 256B). MLP_p1 = 4.

#define B_  8
#define C_  32
#define H_  512
#define W_  512
#define H2 (H_/2)
#define W2 (W_/2)

__global__ void __launch_bounds__(256) haar_dwt2_kernel(
    const float* __restrict__ in, float* __restrict__ out)
{
    // total threads = B*C*(H2/2)*(W2/2) = 8*32*128*128 = 4,194,304
    const int64_t tid = (int64_t)blockIdx.x * blockDim.x + threadIdx.x;

    const int wpair = (int)(tid & (W2/2 - 1));           // 0..127 (2 output cols)
    const int hq    = (int)((tid >> 7) & (H2/2 - 1));    // 0..127 (2 output rows)
    const int bc    = (int)(tid >> 14);                  // 0..255  (b*32 + c)
    const int b     = bc >> 5;
    const int c     = bc & 31;

    // Input: rows 4*hq .. 4*hq+3, cols 4*wpair .. 4*wpair+3
    const int64_t in_base = ((int64_t)bc * H_ + 4 * hq) * W_ + 4 * wpair;
    const float4 r0 = *reinterpret_cast<const float4*>(in + in_base);
    const float4 r1 = *reinterpret_cast<const float4*>(in + in_base + W_);
    const float4 r2 = *reinterpret_cast<const float4*>(in + in_base + 2 * W_);
    const float4 r3 = *reinterpret_cast<const float4*>(in + in_base + 3 * W_);

    // Output row 0 (h2 = 2*hq): from r0 (top) / r1 (bottom)
    float2 LL0, LH0, HL0, HH0;
    LL0.x = (r0.x + r0.y + r1.x + r1.y) * 0.5f;
    LH0.x = (r0.x + r0.y - r1.x - r1.y) * 0.5f;
    HL0.x = (r0.x - r0.y + r1.x - r1.y) * 0.5f;
    HH0.x = (r0.x - r0.y - r1.x + r1.y) * 0.5f;
    LL0.y = (r0.z + r0.w + r1.z + r1.w) * 0.5f;
    LH0.y = (r0.z + r0.w - r1.z - r1.w) * 0.5f;
    HL0.y = (r0.z - r0.w + r1.z - r1.w) * 0.5f;
    HH0.y = (r0.z - r0.w - r1.z + r1.w) * 0.5f;

    // Output row 1 (h2 = 2*hq+1): from r2 (top) / r3 (bottom)
    float2 LL1, LH1, HL1, HH1;
    LL1.x = (r2.x + r2.y + r3.x + r3.y) * 0.5f;
    LH1.x = (r2.x + r2.y - r3.x - r3.y) * 0.5f;
    HL1.x = (r2.x - r2.y + r3.x - r3.y) * 0.5f;
    HH1.x = (r2.x - r2.y - r3.x + r3.y) * 0.5f;
    LL1.y = (r2.z + r2.w + r3.z + r3.w) * 0.5f;
    LH1.y = (r2.z + r2.w - r3.z - r3.w) * 0.5f;
    HL1.y = (r2.z - r2.w + r3.z - r3.w) * 0.5f;
    HH1.y = (r2.z - r2.w - r3.z + r3.w) * 0.5f;

    // Output: [B, 4, C, H2, W2]
    const int64_t plane = (int64_t)H2 * W2;                        // 65536
    const int64_t obase = (((int64_t)b * 4) * C_ + c) * plane
                          + (int64_t)(2 * hq) * W2 + 2 * wpair;
    const int64_t sstride = (int64_t)C_ * plane;                   // subband stride

    *reinterpret_cast<float2*>(out + obase)                    = LL0;
    *reinterpret_cast<float2*>(out + obase + W2)               = LL1;
    *reinterpret_cast<float2*>(out + obase + sstride)          = LH0;
    *reinterpret_cast<float2*>(out + obase + sstride + W2)     = LH1;
    *reinterpret_cast<float2*>(out + obase + 2 * sstride)      = HL0;
    *reinterpret_cast<float2*>(out + obase + 2 * sstride + W2) = HL1;
    *reinterpret_cast<float2*>(out + obase + 3 * sstride)      = HH0;
    *reinterpret_cast<float2*>(out + obase + 3 * sstride + W2) = HH1;
}

extern "C" void kernel_launch(void* const* d_in, const int* in_sizes, int n_in,
                              void* d_out, int out_size)
{
    const float* in = (const float*)d_in[0];
    float* out = (float*)d_out;

    const int64_t total_threads = (int64_t)B_ * C_ * (H2/2) * (W2/2);  // 4,194,304
    const int threads = 256;
    const int blocks = (int)(total_threads / threads);                  // 16,384

    haar_dwt2_kernel<<<blocks, threads>>>(in, out);
}